// round 13
// baseline (speedup 1.0000x reference)
#include <cuda_runtime.h>
#include <math.h>

#define BB 16
#define SS 1024
#define NIN 7
#define NHID 28
#define HEADS 7
#define HD 4

// Scratch (device globals — no allocation allowed)
__device__ float g_Q [BB*HEADS*SS*HD];
__device__ float g_K [BB*HEADS*SS*HD];
__device__ float g_V [BB*HEADS*SS*HD];
__device__ float g_AO[BB*SS*NHID];
__device__ float g_Q2[BB*SS*NHID];
__device__ float g_K2[BB*SS*NHID];

// ---------------------------------------------------------------------------
// helpers
// ---------------------------------------------------------------------------
typedef unsigned long long u64;
__device__ __forceinline__ float ex2(float x) {            // single MUFU.EX2
    float r; asm("ex2.approx.ftz.f32 %0, %1;" : "=f"(r) : "f"(x)); return r;
}
__device__ __forceinline__ u64 pk2(float a, float b) {
    u64 r; asm("mov.b64 %0, {%1,%2};" : "=l"(r) : "f"(a), "f"(b)); return r;
}
__device__ __forceinline__ void up2(u64 v, float& a, float& b) {
    asm("mov.b64 {%0,%1}, %2;" : "=f"(a), "=f"(b) : "l"(v));
}
__device__ __forceinline__ u64 f2fma(u64 a, u64 b, u64 c) {
    u64 d; asm("fma.rn.f32x2 %0, %1, %2, %3;" : "=l"(d) : "l"(a), "l"(b), "l"(c)); return d;
}
__device__ __forceinline__ u64 f2mul(u64 a, u64 b) {
    u64 d; asm("mul.rn.f32x2 %0, %1, %2;" : "=l"(d) : "l"(a), "l"(b)); return d;
}
__device__ __forceinline__ u64 f2add(u64 a, u64 b) {
    u64 d; asm("add.rn.f32x2 %0, %1, %2;" : "=l"(d) : "l"(a), "l"(b)); return d;
}

// ---------------------------------------------------------------------------
// K1: QKV projection. 1 thread per (b,s) row. Q/K/V stored [B,H,S,4] (float4).
// ---------------------------------------------------------------------------
__global__ void k_qkv(const float* __restrict__ x,
                      const float* __restrict__ Wq, const float* __restrict__ bq,
                      const float* __restrict__ Wk, const float* __restrict__ bk,
                      const float* __restrict__ Wv, const float* __restrict__ bv) {
    __shared__ float sw[672];
    int tid = threadIdx.x;
    for (int i = tid; i < 196; i += blockDim.x) {
        sw[i] = Wq[i]; sw[224 + i] = Wk[i]; sw[448 + i] = Wv[i];
    }
    if (tid < 28) { sw[196 + tid] = bq[tid]; sw[420 + tid] = bk[tid]; sw[644 + tid] = bv[tid]; }
    __syncthreads();

    int r = blockIdx.x * blockDim.x + tid;        // 0..16383
    int b = r >> 10, s = r & 1023;

    float xv[7];
#pragma unroll
    for (int i = 0; i < 7; i++) xv[i] = x[r * 7 + i];

#pragma unroll
    for (int h = 0; h < 7; h++) {
        float qa[4], ka[4], va[4];
#pragma unroll
        for (int d = 0; d < 4; d++) {
            int j = h * 4 + d;
            float aq = sw[196 + j], ak = sw[420 + j], av = sw[644 + j];
#pragma unroll
            for (int i = 0; i < 7; i++) {
                float xi = xv[i];
                aq += xi * sw[i * 28 + j];
                ak += xi * sw[224 + i * 28 + j];
                av += xi * sw[448 + i * 28 + j];
            }
            qa[d] = aq; ka[d] = ak; va[d] = av;
        }
        int o = (b * 7 + h) * 1024 + s;
        reinterpret_cast<float4*>(g_Q)[o] = make_float4(qa[0], qa[1], qa[2], qa[3]);
        reinterpret_cast<float4*>(g_K)[o] = make_float4(ka[0], ka[1], ka[2], ka[3]);
        reinterpret_cast<float4*>(g_V)[o] = make_float4(va[0], va[1], va[2], va[3]);
    }
}

// ---------------------------------------------------------------------------
// K2: first attention — 2 q rows x 4 k per iteration, f32x2 over k-pairs.
// Kt/Vt transposed-paired in smem (32KB). 4 independent score chains,
// 8 ex2 batched back-to-back (MUFU latency amortized).
// Grid (4,7,16)=448, 128 thr.
// ---------------------------------------------------------------------------
__global__ void __launch_bounds__(128) k_attn1() {
    __shared__ ulonglong2 Kt[1024];
    __shared__ ulonglong2 Vt[1024];
    int b = blockIdx.z, h = blockIdx.y, chunk = blockIdx.x;   // chunk in [0,4)
    int bh = b * 7 + h;
    const float4* Kg = reinterpret_cast<const float4*>(g_K) + bh * 1024;
    const float4* Vg = reinterpret_cast<const float4*>(g_V) + bh * 1024;
    for (int p = threadIdx.x; p < 512; p += 128) {
        float4 a = Kg[2*p], c2 = Kg[2*p+1];
        Kt[2*p]   = make_ulonglong2(pk2(a.x, c2.x), pk2(a.y, c2.y));
        Kt[2*p+1] = make_ulonglong2(pk2(a.z, c2.z), pk2(a.w, c2.w));
        float4 va = Vg[2*p], vc = Vg[2*p+1];
        Vt[2*p]   = make_ulonglong2(pk2(va.x, vc.x), pk2(va.y, vc.y));
        Vt[2*p+1] = make_ulonglong2(pk2(va.z, vc.z), pk2(va.w, vc.w));
    }
    __syncthreads();

    int qA = chunk * 256 + threadIdx.x;           // rows qA, qA+128
    const float c = 0.5f * 1.4426950408889634f;   // 1/sqrt(4) * log2(e)
    float4 q0 = reinterpret_cast<const float4*>(g_Q)[bh * 1024 + qA];
    float4 q1 = reinterpret_cast<const float4*>(g_Q)[bh * 1024 + qA + 128];
    u64 q0d0 = pk2(q0.x * c, q0.x * c), q0d1 = pk2(q0.y * c, q0.y * c);
    u64 q0d2 = pk2(q0.z * c, q0.z * c), q0d3 = pk2(q0.w * c, q0.w * c);
    u64 q1d0 = pk2(q1.x * c, q1.x * c), q1d1 = pk2(q1.y * c, q1.y * c);
    u64 q1d2 = pk2(q1.z * c, q1.z * c), q1d3 = pk2(q1.w * c, q1.w * c);

    u64 a00 = 0ull, a01 = 0ull, a02 = 0ull, a03 = 0ull, l0 = 0ull;
    u64 a10 = 0ull, a11 = 0ull, a12 = 0ull, a13 = 0ull, l1 = 0ull;
#pragma unroll 2
    for (int p = 0; p < 256; p++) {               // 4 k (2 pairs) per iter
        ulonglong2 kA01 = Kt[4*p],   kA23 = Kt[4*p+1];
        ulonglong2 kB01 = Kt[4*p+2], kB23 = Kt[4*p+3];
        u64 s0a = f2mul(q0d0, kA01.x);
        u64 s0b = f2mul(q0d0, kB01.x);
        u64 s1a = f2mul(q1d0, kA01.x);
        u64 s1b = f2mul(q1d0, kB01.x);
        s0a = f2fma(q0d1, kA01.y, s0a);  s0b = f2fma(q0d1, kB01.y, s0b);
        s1a = f2fma(q1d1, kA01.y, s1a);  s1b = f2fma(q1d1, kB01.y, s1b);
        s0a = f2fma(q0d2, kA23.x, s0a);  s0b = f2fma(q0d2, kB23.x, s0b);
        s1a = f2fma(q1d2, kA23.x, s1a);  s1b = f2fma(q1d2, kB23.x, s1b);
        s0a = f2fma(q0d3, kA23.y, s0a);  s0b = f2fma(q0d3, kB23.y, s0b);
        s1a = f2fma(q1d3, kA23.y, s1a);  s1b = f2fma(q1d3, kB23.y, s1b);
        float w0,w1,w2,w3,w4,w5,w6,w7;
        up2(s0a, w0, w1); up2(s0b, w2, w3);
        up2(s1a, w4, w5); up2(s1b, w6, w7);
        float e0 = ex2(w0), e1 = ex2(w1), e2 = ex2(w2), e3 = ex2(w3);
        float e4 = ex2(w4), e5 = ex2(w5), e6 = ex2(w6), e7 = ex2(w7);
        u64 p0a = pk2(e0, e1), p0b = pk2(e2, e3);
        u64 p1a = pk2(e4, e5), p1b = pk2(e6, e7);
        ulonglong2 vA01 = Vt[4*p],   vA23 = Vt[4*p+1];
        ulonglong2 vB01 = Vt[4*p+2], vB23 = Vt[4*p+3];
        a00 = f2fma(p0a, vA01.x, a00);  a10 = f2fma(p1a, vA01.x, a10);
        a01 = f2fma(p0a, vA01.y, a01);  a11 = f2fma(p1a, vA01.y, a11);
        a02 = f2fma(p0a, vA23.x, a02);  a12 = f2fma(p1a, vA23.x, a12);
        a03 = f2fma(p0a, vA23.y, a03);  a13 = f2fma(p1a, vA23.y, a13);
        a00 = f2fma(p0b, vB01.x, a00);  a10 = f2fma(p1b, vB01.x, a10);
        a01 = f2fma(p0b, vB01.y, a01);  a11 = f2fma(p1b, vB01.y, a11);
        a02 = f2fma(p0b, vB23.x, a02);  a12 = f2fma(p1b, vB23.x, a12);
        a03 = f2fma(p0b, vB23.y, a03);  a13 = f2fma(p1b, vB23.y, a13);
        l0 = f2add(l0, p0a);  l1 = f2add(l1, p1a);
        l0 = f2add(l0, p0b);  l1 = f2add(l1, p1b);
    }
    {
        float le, lo; up2(l0, le, lo);
        float inv = 1.f / (le + lo);
        float e0,o0,e1,o1,e2,o2,e3,o3;
        up2(a00, e0, o0); up2(a01, e1, o1); up2(a02, e2, o2); up2(a03, e3, o3);
        *reinterpret_cast<float4*>(g_AO + ((b * 1024 + qA) * 28 + h * 4)) =
            make_float4((e0+o0)*inv, (e1+o1)*inv, (e2+o2)*inv, (e3+o3)*inv);
    }
    {
        float le, lo; up2(l1, le, lo);
        float inv = 1.f / (le + lo);
        float e0,o0,e1,o1,e2,o2,e3,o3;
        up2(a10, e0, o0); up2(a11, e1, o1); up2(a12, e2, o2); up2(a13, e3, o3);
        *reinterpret_cast<float4*>(g_AO + ((b * 1024 + qA + 128) * 28 + h * 4)) =
            make_float4((e0+o0)*inv, (e1+o1)*inv, (e2+o2)*inv, (e3+o3)*inv);
    }
}

// ---------------------------------------------------------------------------
// K3: LayerNorm(28) + FFN(28->7) + ReLU + residual -> out7 (d_out head),
// then Q2/K2 projections (7->28) into scratch. 1 thread per row.
// ---------------------------------------------------------------------------
__global__ void k_lnffn(const float* __restrict__ x,
                        const float* __restrict__ lnw, const float* __restrict__ lnb,
                        const float* __restrict__ W1,  const float* __restrict__ b1,
                        const float* __restrict__ Wq2, const float* __restrict__ bq2,
                        const float* __restrict__ Wk2, const float* __restrict__ bk2,
                        float* __restrict__ out7) {
    __shared__ float s_lnw[28], s_lnb[28], s_W1[196], s_b1[7];
    __shared__ float s_Wq2[196], s_bq2[28], s_Wk2[196], s_bk2[28];
    int tid = threadIdx.x;
    for (int i = tid; i < 196; i += blockDim.x) { s_W1[i] = W1[i]; s_Wq2[i] = Wq2[i]; s_Wk2[i] = Wk2[i]; }
    if (tid < 28) { s_lnw[tid] = lnw[tid]; s_lnb[tid] = lnb[tid]; s_bq2[tid] = bq2[tid]; s_bk2[tid] = bk2[tid]; }
    if (tid < 7)  { s_b1[tid] = b1[tid]; }
    __syncthreads();

    int r = blockIdx.x * blockDim.x + tid;
    float a[28];
    const float4* ap = reinterpret_cast<const float4*>(g_AO + r * 28);
#pragma unroll
    for (int i = 0; i < 7; i++) {
        float4 t = ap[i];
        a[4*i] = t.x; a[4*i+1] = t.y; a[4*i+2] = t.z; a[4*i+3] = t.w;
    }
    float mu = 0.f;
#pragma unroll
    for (int j = 0; j < 28; j++) mu += a[j];
    mu *= (1.f / 28.f);
    float var = 0.f;
#pragma unroll
    for (int j = 0; j < 28; j++) { float d = a[j] - mu; var += d * d; }
    var *= (1.f / 28.f);
    float rs = rsqrtf(var + 1e-5f);

    float y[28];
#pragma unroll
    for (int j = 0; j < 28; j++) y[j] = (a[j] - mu) * rs * s_lnw[j] + s_lnb[j];

    float z[7];
#pragma unroll
    for (int i = 0; i < 7; i++) {
        float t = s_b1[i];
#pragma unroll
        for (int j = 0; j < 28; j++) t += y[j] * s_W1[j * 7 + i];
        t = fmaxf(t, 0.f) + x[r * 7 + i];
        z[i] = t;
        out7[r * 7 + i] = t;
    }
#pragma unroll
    for (int j = 0; j < 28; j++) {
        float tq = s_bq2[j], tk = s_bk2[j];
#pragma unroll
        for (int i = 0; i < 7; i++) {
            tq += z[i] * s_Wq2[i * 28 + j];
            tk += z[i] * s_Wk2[i * 28 + j];
        }
        g_Q2[r * 28 + j] = tq;
        g_K2[r * 28 + j] = tk;
    }
}

// ---------------------------------------------------------------------------
// K4: second attention weights — 4 ADJACENT k rows per thread in registers,
// 256 threads cover all 1024 k. Per q-iter: 7 broadcast LDS + 56 f2fma in
// 4 independent chains + 4 ex2 + ONE STG.128. LSU ops per unit work halved
// vs the 2-row/512-thr version. Two-pass normalize (warp owns 4 q-rows).
// ---------------------------------------------------------------------------
__global__ void __launch_bounds__(256, 1) k_attn2(float* __restrict__ out) {
    __shared__ float sQ[32 * 28];          // q tile (scaled)

    int b = blockIdx.y, tile = blockIdx.x;             // 32 tiles of 32 q rows
    int warp = threadIdx.x >> 5, lane = threadIdx.x & 31;
    const float SC2 = 1.4426950408889634f / 2.6457513110645906f; // log2(e)/sqrt(7)

    for (int t = threadIdx.x; t < 32 * 28; t += 256)
        sQ[t] = g_Q2[(b * 1024 + tile * 32) * 28 + t] * SC2;

    int m = threadIdx.x;                                // k rows 4m..4m+3
    ulonglong2 kR[4][7];
    {
#pragma unroll
        for (int r = 0; r < 4; r++) {
            const ulonglong2* src =
                reinterpret_cast<const ulonglong2*>(g_K2 + (b * 1024 + 4 * m + r) * 28);
#pragma unroll
            for (int j = 0; j < 7; j++) kR[r][j] = src[j];
        }
    }
    __syncthreads();

    float* obase = out + (b * 1024 + tile * 32) * 1024;

#pragma unroll 2
    for (int q = 0; q < 32; q++) {
        const ulonglong2* qp = reinterpret_cast<const ulonglong2*>(sQ + q * 28);
        ulonglong2 qv[7];
#pragma unroll
        for (int j = 0; j < 7; j++) qv[j] = qp[j];      // broadcast LDS (N=1)

        float p[4];
#pragma unroll
        for (int r = 0; r < 4; r++) {
            u64 acc = f2mul(qv[0].x, kR[r][0].x);
            acc = f2fma(qv[0].y, kR[r][0].y, acc);
            acc = f2fma(qv[1].x, kR[r][1].x, acc);
            acc = f2fma(qv[1].y, kR[r][1].y, acc);
            acc = f2fma(qv[2].x, kR[r][2].x, acc);
            acc = f2fma(qv[2].y, kR[r][2].y, acc);
            acc = f2fma(qv[3].x, kR[r][3].x, acc);
            acc = f2fma(qv[3].y, kR[r][3].y, acc);
            acc = f2fma(qv[4].x, kR[r][4].x, acc);
            acc = f2fma(qv[4].y, kR[r][4].y, acc);
            acc = f2fma(qv[5].x, kR[r][5].x, acc);
            acc = f2fma(qv[5].y, kR[r][5].y, acc);
            acc = f2fma(qv[6].x, kR[r][6].x, acc);
            acc = f2fma(qv[6].y, kR[r][6].y, acc);
            float lo, hi; up2(acc, lo, hi);
            p[r] = ex2(lo + hi);
        }
        // one STG.128 at columns 4m..4m+3 (16B aligned)
        *reinterpret_cast<float4*>(&obase[q * 1024 + 4 * m]) =
            make_float4(p[0], p[1], p[2], p[3]);
    }
    __syncthreads();   // make all warps' global p-writes visible block-wide

    // Normalize pass: each warp owns 4 q-rows {4*warp .. 4*warp+3}.
#pragma unroll
    for (int rr = 0; rr < 4; rr++) {
        int q = warp * 4 + rr;
        float4* row = reinterpret_cast<float4*>(obase + q * 1024);
        float4 v[8];
#pragma unroll
        for (int i = 0; i < 8; i++) v[i] = row[i * 32 + lane];
        float s = 0.f;
#pragma unroll
        for (int i = 0; i < 8; i++) s += (v[i].x + v[i].y) + (v[i].z + v[i].w);
#pragma unroll
        for (int o = 16; o > 0; o >>= 1)
            s += __shfl_xor_sync(0xffffffffu, s, o);
        float iv = 1.f / s;
#pragma unroll
        for (int i = 0; i < 8; i++) {
            v[i].x *= iv; v[i].y *= iv; v[i].z *= iv; v[i].w *= iv;
            row[i * 32 + lane] = v[i];
        }
    }
}

// ---------------------------------------------------------------------------
extern "C" void kernel_launch(void* const* d_in, const int* in_sizes, int n_in,
                              void* d_out, int out_size) {
    const float* x    = (const float*)d_in[0];
    const float* Wq   = (const float*)d_in[1];
    const float* bq   = (const float*)d_in[2];
    const float* Wk   = (const float*)d_in[3];
    const float* bk   = (const float*)d_in[4];
    const float* Wv   = (const float*)d_in[5];
    const float* bv   = (const float*)d_in[6];
    const float* lnw  = (const float*)d_in[7];
    const float* lnb  = (const float*)d_in[8];
    const float* W1   = (const float*)d_in[9];
    const float* b1   = (const float*)d_in[10];
    const float* Wq2  = (const float*)d_in[11];
    const float* bq2  = (const float*)d_in[12];
    const float* Wk2  = (const float*)d_in[13];
    const float* bk2  = (const float*)d_in[14];
    float* out = (float*)d_out;

    k_qkv<<<128, 128>>>(x, Wq, bq, Wk, bk, Wv, bv);
    k_attn1<<<dim3(4, 7, 16), 128>>>();
    k_lnffn<<<128, 128>>>(x, lnw, lnb, W1, b1, Wq2, bq2, Wk2, bk2, out);
    k_attn2<<<dim3(32, 16), 256>>>(out + BB * SS * NIN);
}